// round 14
// baseline (speedup 1.0000x reference)
#include <cuda_runtime.h>
#include <cuda_fp16.h>
#include <math.h>
#include <stdint.h>

#define NMAX      500000
#define DIM       128
#define SNEG      256
#define BSTRIDE   144          // byte stride of int8 rows in smem: 16B-aligned, LDSM conflict-free
#define MTILE     128          // rows per tile
#define INV_T     10.0f
#define LOG_S     5.545177444479562f    // log(256)
#define EXSCALE   14.426950408889634f   // INV_T * log2(e)
#define GRIDP     444                   // persistent blocks (3 per SM)
#define MAXBLOCKS 8192

// int8 quantized normalized embeddings + per-row dequant scale:
//   cos(a,b) = dot_int8(a,b) * sc[a] * sc[b]
__device__ int8_t   g_Qi[(size_t)NMAX * DIM];
__device__ float    g_sc[NMAX];
__device__ int8_t   g_Vq[SNEG * DIM];   // negatives at COMMON scale
__device__ float    g_negsc;            // common dequant scale for g_Vq
__device__ float    g_partial[MAXBLOCKS];
__device__ unsigned g_done;

// ---------------------------------------------------------------------------
// Kernel 1: normalize + per-row maxabs int8 quantize. One warp per row.
// ---------------------------------------------------------------------------
__global__ void quantize_kernel(const float* __restrict__ E, int n) {
    int row  = (int)((blockIdx.x * (long long)blockDim.x + threadIdx.x) >> 5);
    int lane = threadIdx.x & 31;
    if (row >= n) return;
    float4 v = reinterpret_cast<const float4*>(E + (size_t)row * DIM)[lane];
    float ss = v.x * v.x + v.y * v.y + v.z * v.z + v.w * v.w;
    float ma = fmaxf(fmaxf(fabsf(v.x), fabsf(v.y)), fmaxf(fabsf(v.z), fabsf(v.w)));
#pragma unroll
    for (int o = 16; o > 0; o >>= 1) {
        ss += __shfl_xor_sync(0xffffffffu, ss, o);
        ma  = fmaxf(ma, __shfl_xor_sync(0xffffffffu, ma, o));
    }
    float inv = 1.0f / fmaxf(sqrtf(ss), 1e-12f);
    float qs  = 127.0f / fmaxf(ma, 1e-20f);
    int q0 = __float2int_rn(v.x * qs);
    int q1 = __float2int_rn(v.y * qs);
    int q2 = __float2int_rn(v.z * qs);
    int q3 = __float2int_rn(v.w * qs);
    unsigned packed = (unsigned)(q0 & 0xFF) | ((unsigned)(q1 & 0xFF) << 8)
                    | ((unsigned)(q2 & 0xFF) << 16) | ((unsigned)(q3 & 0xFF) << 24);
    reinterpret_cast<unsigned*>(g_Qi + (size_t)row * DIM)[lane] = packed;
    if (lane == 0) g_sc[row] = ma * inv * (1.0f / 127.0f);
}

// ---------------------------------------------------------------------------
// Kernel 2: quantize the 256 negatives to ONE common scale (1 block).
// ---------------------------------------------------------------------------
__global__ void negprep_kernel(const float* __restrict__ E,
                               const void* __restrict__ neg_idx, int n) {
    __shared__ float sMax[256];
    int tid = threadIdx.x;

    int ok = 1;
    if (tid < 128) {
        long long v = ((const long long*)neg_idx)[tid];
        ok = (v >= 0 && v < (long long)n);
    }
    const int is64 = __syncthreads_and(ok);

    long long vr = is64 ? ((const long long*)neg_idx)[tid]
                        : (long long)((const int*)neg_idx)[tid];
    const float4* src = reinterpret_cast<const float4*>(E + (size_t)vr * DIM);

    float ss = 0.f, ma = 0.f;
#pragma unroll
    for (int j = 0; j < 32; j++) {
        float4 v = src[j];
        ss += v.x * v.x + v.y * v.y + v.z * v.z + v.w * v.w;
        ma = fmaxf(ma, fmaxf(fmaxf(fabsf(v.x), fabsf(v.y)),
                             fmaxf(fabsf(v.z), fabsf(v.w))));
    }
    float inv = 1.0f / fmaxf(sqrtf(ss), 1e-12f);
    sMax[tid] = ma * inv;          // max |normalized element| of this row
    __syncthreads();
    for (int o = 128; o > 0; o >>= 1) {
        if (tid < o) sMax[tid] = fmaxf(sMax[tid], sMax[tid + o]);
        __syncthreads();
    }
    const float gmax = sMax[0];
    const float qs = 127.0f / gmax * inv;   // x -> int8 at common scale

    unsigned* dst = reinterpret_cast<unsigned*>(g_Vq + tid * DIM);
#pragma unroll
    for (int j = 0; j < 32; j++) {
        float4 v = src[j];                  // L1/L2 hit
        int q0 = __float2int_rn(v.x * qs);
        int q1 = __float2int_rn(v.y * qs);
        int q2 = __float2int_rn(v.z * qs);
        int q3 = __float2int_rn(v.w * qs);
        dst[j] = (unsigned)(q0 & 0xFF) | ((unsigned)(q1 & 0xFF) << 8)
               | ((unsigned)(q2 & 0xFF) << 16) | ((unsigned)(q3 & 0xFF) << 24);
    }
    if (tid == 0) g_negsc = gmax * (1.0f / 127.0f);
}

__device__ __forceinline__ uint32_t smem_u32(const void* p) {
    uint32_t a;
    asm("{ .reg .u64 t; cvta.to.shared.u64 t, %1; cvt.u32.u64 %0, t; }"
        : "=r"(a) : "l"(p));
    return a;
}

__device__ __forceinline__ float ex2f(float x) {
    float y;
    asm("ex2.approx.ftz.f32 %0, %1;" : "=f"(y) : "f"(x));
    return y;
}

// ---------------------------------------------------------------------------
// Kernel 3: persistent main. B (int8, common scale) staged once per block;
// per tile each warp owns 16 rows end-to-end. IMMA m16n8k32, ldmatrix-b16
// trick for int8 B fragments. ex2 epilogue with one fused per-row constant.
// ---------------------------------------------------------------------------
__global__ __launch_bounds__(256, 3) void main_kernel(
    const void* __restrict__ pos_idx,
    float* __restrict__ out,
    int n, int ntiles)
{
    extern __shared__ char smem_raw[];
    char*  sB   = smem_raw;                                     // 256*144 int8
    float* sPos = reinterpret_cast<float*>(sB + SNEG * BSTRIDE);
    float* sRed = sPos + MTILE;
    int*   sLastP = reinterpret_cast<int*>(sRed + 8);

    const int tid  = threadIdx.x;
    const int lane = tid & 31;
    const int warp = tid >> 5;

    // ---- index dtype detection (first 1KB of positives) --------------------
    int ok = 1;
    if (tid < 128) {
        long long v = ((const long long*)pos_idx)[tid];
        ok = (v >= 0 && v < (long long)n);
    }
    const int is64 = __syncthreads_and(ok);

    // ---- stage negatives ONCE: contiguous copy of g_Vq, 144B smem stride ---
    {
        int h8 = lane & 7, r4 = lane >> 3;
#pragma unroll
        for (int i = 0; i < 8; i++) {
            int r = warp * 32 + 4 * i + r4;
            uint4 v = *reinterpret_cast<const uint4*>(g_Vq + r * DIM + h8 * 16);
            *reinterpret_cast<uint4*>(sB + r * BSTRIDE + h8 * 16) = v;
        }
    }
    __syncthreads();

    const float gneg2 = g_negsc * EXSCALE;   // common-scale * 10*log2(e)

    const int half16 = lane & 15;
    const int rsel   = lane >> 4;
    const int g  = lane >> 2;
    const int t4 = lane & 3;

    // ldmatrix per-lane address (4 matrices: 2 n-tiles x k lo/hi 16B)
    const int nrow = (lane & 7) + ((lane & 16) >> 1);
    const uint32_t bAddr = smem_u32(sB) + nrow * BSTRIDE + ((lane & 8) << 1);

    float local = 0.0f;

    for (int tile = blockIdx.x; tile < ntiles; tile += GRIDP) {
        const long long tile0 = (long long)tile * MTILE;

        // ---- positive logits: dp4a, coalesced 16 lanes/row, 2 rows/iter ----
#pragma unroll
        for (int i = 0; i < 8; i++) {
            int rloc = warp * 16 + 2 * i + rsel;
            long long row = tile0 + rloc;
            int d = 0;
            long long p = 0;
            if (row < n) {
                p = is64 ? ((const long long*)pos_idx)[row]
                         : (long long)((const int*)pos_idx)[row];
                uint2 a = *reinterpret_cast<const uint2*>(
                    g_Qi + (size_t)row * DIM + half16 * 8);
                uint2 b = *reinterpret_cast<const uint2*>(
                    g_Qi + (size_t)p * DIM + half16 * 8);
                d = __dp4a((int)a.x, (int)b.x, __dp4a((int)a.y, (int)b.y, 0));
            }
#pragma unroll
            for (int o = 8; o > 0; o >>= 1)
                d += __shfl_xor_sync(0xffffffffu, d, o);
            if (half16 == 0)
                sPos[rloc] = (row < n)
                    ? (float)d * g_sc[row] * g_sc[p] * INV_T : 0.0f;
        }
        __syncwarp();

        // ---- A fragments (int8, m16n8k32) for this warp's 16 rows ----------
        const long long rowG = tile0 + warp * 16 + g;
        const bool v0 = rowG < n, v1 = rowG + 8 < n;
        unsigned afr[4][4];
        {
            const char* p0 = (const char*)g_Qi + (size_t)rowG * DIM + 4 * t4;
            const char* p1 = p0 + 8 * DIM;
#pragma unroll
            for (int ks = 0; ks < 4; ks++) {
                afr[ks][0] = v0 ? *reinterpret_cast<const unsigned*>(p0 + 32 * ks) : 0u;
                afr[ks][1] = v1 ? *reinterpret_cast<const unsigned*>(p1 + 32 * ks) : 0u;
                afr[ks][2] = v0 ? *reinterpret_cast<const unsigned*>(p0 + 16 + 32 * ks) : 0u;
                afr[ks][3] = v1 ? *reinterpret_cast<const unsigned*>(p1 + 16 + 32 * ks) : 0u;
            }
        }
        const float srow2a = (v0 ? g_sc[rowG]     : 0.0f) * gneg2;
        const float srow2b = (v1 ? g_sc[rowG + 8] : 0.0f) * gneg2;

        // ---- GEMM: 8 chunks of 32 negatives, s32 accum ----------------------
        float rs0 = 0.0f, rs1 = 0.0f;
#pragma unroll
        for (int c = 0; c < 8; c++) {
            int acc[4][4];
#pragma unroll
            for (int i = 0; i < 4; i++) {
                acc[i][0] = 0; acc[i][1] = 0; acc[i][2] = 0; acc[i][3] = 0;
            }
#pragma unroll
            for (int ks = 0; ks < 4; ks++) {
#pragma unroll
                for (int p2 = 0; p2 < 2; p2++) {
                    unsigned b0, b1, b2, b3;
                    uint32_t a = bAddr + (c * 32 + p2 * 16) * BSTRIDE + ks * 32;
                    asm volatile(
                        "ldmatrix.sync.aligned.m8n8.x4.shared.b16 "
                        "{%0,%1,%2,%3}, [%4];"
                        : "=r"(b0), "=r"(b1), "=r"(b2), "=r"(b3) : "r"(a));
                    asm volatile(
                        "mma.sync.aligned.m16n8k32.row.col.s32.s8.s8.s32 "
                        "{%0,%1,%2,%3}, {%4,%5,%6,%7}, {%8,%9}, {%0,%1,%2,%3};\n"
                        : "+r"(acc[p2 * 2][0]), "+r"(acc[p2 * 2][1]),
                          "+r"(acc[p2 * 2][2]), "+r"(acc[p2 * 2][3])
                        : "r"(afr[ks][0]), "r"(afr[ks][1]),
                          "r"(afr[ks][2]), "r"(afr[ks][3]),
                          "r"(b0), "r"(b1));
                    asm volatile(
                        "mma.sync.aligned.m16n8k32.row.col.s32.s8.s8.s32 "
                        "{%0,%1,%2,%3}, {%4,%5,%6,%7}, {%8,%9}, {%0,%1,%2,%3};\n"
                        : "+r"(acc[p2 * 2 + 1][0]), "+r"(acc[p2 * 2 + 1][1]),
                          "+r"(acc[p2 * 2 + 1][2]), "+r"(acc[p2 * 2 + 1][3])
                        : "r"(afr[ks][0]), "r"(afr[ks][1]),
                          "r"(afr[ks][2]), "r"(afr[ks][3]),
                          "r"(b2), "r"(b3));
                }
            }
            // epilogue: logit*log2e = I2F(acc) * srow2 -> ex2
#pragma unroll
            for (int nt = 0; nt < 4; nt++) {
                rs0 += ex2f(__int2float_rn(acc[nt][0]) * srow2a)
                     + ex2f(__int2float_rn(acc[nt][1]) * srow2a);
                rs1 += ex2f(__int2float_rn(acc[nt][2]) * srow2b)
                     + ex2f(__int2float_rn(acc[nt][3]) * srow2b);
            }
        }

        rs0 += __shfl_xor_sync(0xffffffffu, rs0, 1);
        rs0 += __shfl_xor_sync(0xffffffffu, rs0, 2);
        rs1 += __shfl_xor_sync(0xffffffffu, rs1, 1);
        rs1 += __shfl_xor_sync(0xffffffffu, rs1, 2);

        if (t4 == 0) {
            if (v0) local += sPos[warp * 16 + g]     - (logf(rs0) - LOG_S);
            if (v1) local += sPos[warp * 16 + g + 8] - (logf(rs1) - LOG_S);
        }
    }

    // ---- deterministic block + grid reduction -------------------------------
#pragma unroll
    for (int o = 16; o > 0; o >>= 1)
        local += __shfl_xor_sync(0xffffffffu, local, o);
    if (lane == 0) sRed[warp] = local;
    __syncthreads();

    if (tid == 0) {
        float s = 0.0f;
#pragma unroll
        for (int w = 0; w < 8; w++) s += sRed[w];
        g_partial[blockIdx.x] = s;
        __threadfence();
        unsigned t = atomicAdd(&g_done, 1u);
        *sLastP = (t == (unsigned)(GRIDP - 1));
    }
    __syncthreads();
    if (*sLastP) {
        float s = 0.0f;
        for (int i = tid; i < GRIDP; i += 256) s += g_partial[i];
#pragma unroll
        for (int o = 16; o > 0; o >>= 1)
            s += __shfl_xor_sync(0xffffffffu, s, o);
        if (lane == 0) sRed[warp] = s;
        __syncthreads();
        if (tid == 0) {
            float tot = 0.f;
#pragma unroll
            for (int w = 0; w < 8; w++) tot += sRed[w];
            out[0] = -tot / (float)n;
            g_done = 0;                  // reset for next graph replay
        }
    }
}

// ---------------------------------------------------------------------------
extern "C" void kernel_launch(void* const* d_in, const int* in_sizes, int n_in,
                              void* d_out, int out_size) {
    const float* E   = (const float*)d_in[0];
    const void*  pos = d_in[1];
    const void*  neg = d_in[2];
    int n = in_sizes[1];   // number of edges

    int nblk_q = (n + 7) / 8;
    quantize_kernel<<<nblk_q, 256>>>(E, n);
    negprep_kernel<<<1, 256>>>(E, neg, n);

    int ntiles = (n + MTILE - 1) / MTILE;
    size_t smem = (size_t)(SNEG * BSTRIDE)
                + (size_t)(MTILE + 8 + 4) * sizeof(float);
    cudaFuncSetAttribute(main_kernel,
                         cudaFuncAttributeMaxDynamicSharedMemorySize, (int)smem);
    main_kernel<<<GRIDP, 256, smem>>>(pos, (float*)d_out, n, ntiles);
}

// round 15
// speedup vs baseline: 1.6710x; 1.6710x over previous
#include <cuda_runtime.h>
#include <cuda_fp16.h>
#include <math.h>
#include <stdint.h>

#define NMAX      500000
#define DIM       128
#define SNEG      256
#define STRIDE    136          // fp16 units -> 272B row stride (16B aligned, LDSM conflict-free)
#define MTILE     256          // rows per tile (32 rows per warp)
#define INV_T     10.0f
#define LOG_S     5.545177444479562f    // log(256)
#define EXSCALE   14.426950408889634f   // INV_T * log2(e), applied in f32 epilogue
#define GRIDP     296                   // persistent blocks (2 per SM)
#define MAXBLOCKS 8192

__device__ __half    g_Qn[(size_t)NMAX * DIM];
__device__ float     g_partial[MAXBLOCKS];
__device__ unsigned  g_done;

// ---------------------------------------------------------------------------
__global__ void normalize_kernel(const float* __restrict__ E, int n) {
    int row  = (int)((blockIdx.x * (long long)blockDim.x + threadIdx.x) >> 5);
    int lane = threadIdx.x & 31;
    if (row >= n) return;
    float4 v = reinterpret_cast<const float4*>(E + (size_t)row * DIM)[lane];
    float ss = v.x * v.x + v.y * v.y + v.z * v.z + v.w * v.w;
#pragma unroll
    for (int o = 16; o > 0; o >>= 1) ss += __shfl_xor_sync(0xffffffffu, ss, o);
    float inv = 1.0f / fmaxf(sqrtf(ss), 1e-12f);
    __half2 p0 = __floats2half2_rn(v.x * inv, v.y * inv);
    __half2 p1 = __floats2half2_rn(v.z * inv, v.w * inv);
    uint2 st;
    st.x = reinterpret_cast<unsigned&>(p0);
    st.y = reinterpret_cast<unsigned&>(p1);
    reinterpret_cast<uint2*>(g_Qn + (size_t)row * DIM)[lane] = st;
}

__device__ __forceinline__ float pairdot(unsigned a, unsigned b) {
    float2 fa = __half22float2(*reinterpret_cast<__half2*>(&a));
    float2 fb = __half22float2(*reinterpret_cast<__half2*>(&b));
    return fa.x * fb.x + fa.y * fb.y;
}

__device__ __forceinline__ uint32_t smem_u32(const void* p) {
    uint32_t a;
    asm("{ .reg .u64 t; cvta.to.shared.u64 t, %1; cvt.u32.u64 %0, t; }"
        : "=r"(a) : "l"(p));
    return a;
}

__device__ __forceinline__ float ex2f(float x) {
    float y;
    asm("ex2.approx.ftz.f32 %0, %1;" : "=f"(y) : "f"(x));
    return y;
}

// ---------------------------------------------------------------------------
// main: persistent blocks; B staged once per block; per tile each warp owns
// 32 rows end-to-end (pos-dot, A fragments, 2 M-tiles of GEMM, lse) -> B
// fragment registers reused across 32 rows, halving LDSM traffic vs 16.
// ---------------------------------------------------------------------------
__global__ __launch_bounds__(256, 2) void main_kernel(
    const void* __restrict__ pos_idx,
    const void* __restrict__ neg_idx,
    float* __restrict__ out,
    int n, int ntiles)
{
    extern __shared__ char smem_raw[];
    __half* sV  = reinterpret_cast<__half*>(smem_raw);          // 256*136 fp16
    float* sPos = reinterpret_cast<float*>(sV + SNEG * STRIDE); // 256 floats
    float* sRed = sPos + MTILE;                                  // 8 floats
    int*   sLastP = reinterpret_cast<int*>(sRed + 8);

    const int tid  = threadIdx.x;
    const int lane = tid & 31;
    const int warp = tid >> 5;

    // ---- inline index-dtype detection (first 1KB of negatives) -------------
    int ok = 1;
    if (tid < 128) {
        long long v = ((const long long*)neg_idx)[tid];
        ok = (v >= 0 && v < (long long)n);
    }
    const int is64 = __syncthreads_and(ok);

    const int half16 = lane & 15;
    const int rsel   = lane >> 4;

    // ---- stage 256 negatives ONCE, coalesced, unscaled ----------------------
    {
#pragma unroll
        for (int i = 0; i < 16; i++) {
            int r = warp * 32 + 2 * i + rsel;
            long long vr = is64 ? ((const long long*)neg_idx)[r]
                                : (long long)((const int*)neg_idx)[r];
            uint4 v = *reinterpret_cast<const uint4*>(
                g_Qn + (size_t)vr * DIM + half16 * 8);
            *reinterpret_cast<uint4*>(sV + r * STRIDE + half16 * 8) = v;
        }
    }
    __syncthreads();

    // ldmatrix lane->row map (x4: two n-tiles x k lo/hi)
    const int nrow = (lane & 7) + ((lane & 16) >> 1);
    const uint32_t bAddr = smem_u32(sV) + nrow * (STRIDE * 2)
                         + ((lane & 8) << 1);

    const int g  = lane >> 2;
    const int t4 = lane & 3;

    float local = 0.0f;

    for (int tile = blockIdx.x; tile < ntiles; tile += GRIDP) {
        const long long tile0 = (long long)tile * MTILE;

        // ---- positive logits for this warp's 32 rows (coalesced) -----------
#pragma unroll
        for (int i = 0; i < 16; i++) {
            int rloc = warp * 32 + 2 * i + rsel;
            long long row = tile0 + rloc;
            float d = 0.0f;
            if (row < n) {
                long long p = is64 ? ((const long long*)pos_idx)[row]
                                   : (long long)((const int*)pos_idx)[row];
                uint4 a = *reinterpret_cast<const uint4*>(
                    g_Qn + (size_t)row * DIM + half16 * 8);
                uint4 b = *reinterpret_cast<const uint4*>(
                    g_Qn + (size_t)p * DIM + half16 * 8);
                d = pairdot(a.x, b.x) + pairdot(a.y, b.y)
                  + pairdot(a.z, b.z) + pairdot(a.w, b.w);
            }
#pragma unroll
            for (int o = 8; o > 0; o >>= 1)
                d += __shfl_xor_sync(0xffffffffu, d, o);
            if (half16 == 0) sPos[rloc] = d * INV_T;
        }
        __syncwarp();   // sPos produced and consumed within this warp only

        // ---- A fragments for this warp's 32 rows (2 M-tiles of 16) ---------
        const long long rowG = tile0 + warp * 32 + g;
        unsigned afr[2][8][4];
#pragma unroll
        for (int T = 0; T < 2; T++) {
            long long r0 = rowG + 16 * T, r1 = r0 + 8;
            const bool v0 = r0 < n, v1 = r1 < n;
            const unsigned* p0 = reinterpret_cast<const unsigned*>(
                g_Qn + (size_t)r0 * DIM + 2 * t4);
            const unsigned* p1 = reinterpret_cast<const unsigned*>(
                g_Qn + (size_t)r1 * DIM + 2 * t4);
#pragma unroll
            for (int k0 = 0; k0 < 8; k0++) {
                afr[T][k0][0] = v0 ? p0[k0 * 8]     : 0u;
                afr[T][k0][1] = v1 ? p1[k0 * 8]     : 0u;
                afr[T][k0][2] = v0 ? p0[k0 * 8 + 4] : 0u;
                afr[T][k0][3] = v1 ? p1[k0 * 8 + 4] : 0u;
            }
        }

        // ---- GEMM: 8 chunks of 32 negatives; B frags reused by 2 M-tiles ---
        float rs[2][2] = {{0.f, 0.f}, {0.f, 0.f}};
#pragma unroll
        for (int c = 0; c < 8; c++) {
            float acc[2][4][4];
#pragma unroll
            for (int T = 0; T < 2; T++)
#pragma unroll
                for (int i = 0; i < 4; i++) {
                    acc[T][i][0] = 0.f; acc[T][i][1] = 0.f;
                    acc[T][i][2] = 0.f; acc[T][i][3] = 0.f;
                }
#pragma unroll
            for (int k0 = 0; k0 < 8; k0++) {
#pragma unroll
                for (int p2 = 0; p2 < 2; p2++) {
                    unsigned b0, b1, b2, b3;
                    uint32_t a = bAddr + (c * 32 + p2 * 16) * (STRIDE * 2)
                               + k0 * 32;
                    asm volatile(
                        "ldmatrix.sync.aligned.m8n8.x4.shared.b16 "
                        "{%0,%1,%2,%3}, [%4];"
                        : "=r"(b0), "=r"(b1), "=r"(b2), "=r"(b3) : "r"(a));
#pragma unroll
                    for (int T = 0; T < 2; T++) {
                        asm volatile(
                            "mma.sync.aligned.m16n8k16.row.col.f32.f16.f16.f32 "
                            "{%0,%1,%2,%3}, {%4,%5,%6,%7}, {%8,%9}, {%0,%1,%2,%3};\n"
                            : "+f"(acc[T][p2 * 2][0]), "+f"(acc[T][p2 * 2][1]),
                              "+f"(acc[T][p2 * 2][2]), "+f"(acc[T][p2 * 2][3])
                            : "r"(afr[T][k0][0]), "r"(afr[T][k0][1]),
                              "r"(afr[T][k0][2]), "r"(afr[T][k0][3]),
                              "r"(b0), "r"(b1));
                        asm volatile(
                            "mma.sync.aligned.m16n8k16.row.col.f32.f16.f16.f32 "
                            "{%0,%1,%2,%3}, {%4,%5,%6,%7}, {%8,%9}, {%0,%1,%2,%3};\n"
                            : "+f"(acc[T][p2 * 2 + 1][0]), "+f"(acc[T][p2 * 2 + 1][1]),
                              "+f"(acc[T][p2 * 2 + 1][2]), "+f"(acc[T][p2 * 2 + 1][3])
                            : "r"(afr[T][k0][0]), "r"(afr[T][k0][1]),
                              "r"(afr[T][k0][2]), "r"(afr[T][k0][3]),
                              "r"(b2), "r"(b3));
                    }
                }
            }
            // epilogue: exp via ex2(dot * 10*log2e), f32
#pragma unroll
            for (int T = 0; T < 2; T++)
#pragma unroll
                for (int nt = 0; nt < 4; nt++) {
                    rs[T][0] += ex2f(acc[T][nt][0] * EXSCALE)
                              + ex2f(acc[T][nt][1] * EXSCALE);
                    rs[T][1] += ex2f(acc[T][nt][2] * EXSCALE)
                              + ex2f(acc[T][nt][3] * EXSCALE);
                }
        }

#pragma unroll
        for (int T = 0; T < 2; T++) {
            rs[T][0] += __shfl_xor_sync(0xffffffffu, rs[T][0], 1);
            rs[T][0] += __shfl_xor_sync(0xffffffffu, rs[T][0], 2);
            rs[T][1] += __shfl_xor_sync(0xffffffffu, rs[T][1], 1);
            rs[T][1] += __shfl_xor_sync(0xffffffffu, rs[T][1], 2);
        }

        if (t4 == 0) {
#pragma unroll
            for (int T = 0; T < 2; T++) {
                long long r0 = rowG + 16 * T;
                if (r0 < n)
                    local += sPos[warp * 32 + 16 * T + g]
                           - (logf(rs[T][0]) - LOG_S);
                if (r0 + 8 < n)
                    local += sPos[warp * 32 + 16 * T + g + 8]
                           - (logf(rs[T][1]) - LOG_S);
            }
        }
    }

    // ---- deterministic block + grid reduction -------------------------------
#pragma unroll
    for (int o = 16; o > 0; o >>= 1)
        local += __shfl_xor_sync(0xffffffffu, local, o);
    if (lane == 0) sRed[warp] = local;
    __syncthreads();

    if (tid == 0) {
        float s = 0.0f;
#pragma unroll
        for (int w = 0; w < 8; w++) s += sRed[w];
        g_partial[blockIdx.x] = s;
        __threadfence();
        unsigned t = atomicAdd(&g_done, 1u);
        *sLastP = (t == (unsigned)(GRIDP - 1));
    }
    __syncthreads();
    if (*sLastP) {
        float s = 0.0f;
        for (int i = tid; i < GRIDP; i += 256) s += g_partial[i];
#pragma unroll
        for (int o = 16; o > 0; o >>= 1)
            s += __shfl_xor_sync(0xffffffffu, s, o);
        if (lane == 0) sRed[warp] = s;
        __syncthreads();
        if (tid == 0) {
            float tot = 0.f;
#pragma unroll
            for (int w = 0; w < 8; w++) tot += sRed[w];
            out[0] = -tot / (float)n;
            g_done = 0;                  // reset for next graph replay
        }
    }
}

// ---------------------------------------------------------------------------
extern "C" void kernel_launch(void* const* d_in, const int* in_sizes, int n_in,
                              void* d_out, int out_size) {
    const float* E   = (const float*)d_in[0];
    const void*  pos = d_in[1];
    const void*  neg = d_in[2];
    int n = in_sizes[1];   // number of edges

    int nblk_norm = (n + 7) / 8;
    normalize_kernel<<<nblk_norm, 256>>>(E, n);

    int ntiles = (n + MTILE - 1) / MTILE;
    size_t smem = (size_t)(SNEG * STRIDE) * sizeof(__half)
                + (size_t)(MTILE + 8 + 4) * sizeof(float);
    cudaFuncSetAttribute(main_kernel,
                         cudaFuncAttributeMaxDynamicSharedMemorySize, (int)smem);
    main_kernel<<<GRIDP, 256, smem>>>(pos, neg, (float*)d_out, n, ntiles);
}

// round 16
// speedup vs baseline: 1.9942x; 1.1934x over previous
#include <cuda_runtime.h>
#include <cuda_fp16.h>
#include <math.h>
#include <stdint.h>

#define NMAX      500000
#define DIM       128
#define SNEG      256
#define STRIDE    136          // fp16 units -> 272B row stride (16B aligned, LDSM conflict-free)
#define MTILE     128          // rows per tile (16 rows per warp)
#define INV_T     10.0f
#define LOG_S     5.545177444479562f    // log(256)
#define EXSCALE   14.426950408889634f   // INV_T * log2(e), applied in f32 epilogue
#define LN2       0.6931471805599453f
#define GRIDP     444                   // persistent blocks (3 per SM)
#define MAXBLOCKS 8192

__device__ __half    g_Qn[(size_t)NMAX * DIM];
__device__ float     g_partial[MAXBLOCKS];
__device__ unsigned  g_done;

// ---------------------------------------------------------------------------
// normalize: 2 rows per warp (lanes 0-15 row0, 16-31 row1), 1KB per warp.
// ---------------------------------------------------------------------------
__global__ void normalize_kernel(const float* __restrict__ E, int n) {
    long long wid = ((blockIdx.x * (long long)blockDim.x + threadIdx.x) >> 5);
    int lane = threadIdx.x & 31;
    int h16  = lane & 15;
    long long row = wid * 2 + (lane >> 4);
    long long rowc = row < n ? row : (long long)(n - 1);

    const float4* src = reinterpret_cast<const float4*>(E + (size_t)rowc * DIM)
                      + h16 * 2;
    float4 a = src[0], b = src[1];
    float ss = a.x * a.x + a.y * a.y + a.z * a.z + a.w * a.w
             + b.x * b.x + b.y * b.y + b.z * b.z + b.w * b.w;
#pragma unroll
    for (int o = 8; o > 0; o >>= 1) ss += __shfl_xor_sync(0xffffffffu, ss, o);
    float inv = 1.0f / fmaxf(sqrtf(ss), 1e-12f);

    __half2 p0 = __floats2half2_rn(a.x * inv, a.y * inv);
    __half2 p1 = __floats2half2_rn(a.z * inv, a.w * inv);
    __half2 p2 = __floats2half2_rn(b.x * inv, b.y * inv);
    __half2 p3 = __floats2half2_rn(b.z * inv, b.w * inv);
    uint4 st;
    st.x = reinterpret_cast<unsigned&>(p0);
    st.y = reinterpret_cast<unsigned&>(p1);
    st.z = reinterpret_cast<unsigned&>(p2);
    st.w = reinterpret_cast<unsigned&>(p3);
    if (row < n)
        *reinterpret_cast<uint4*>(g_Qn + (size_t)row * DIM + h16 * 8) = st;
}

__device__ __forceinline__ float pairdot(unsigned a, unsigned b) {
    float2 fa = __half22float2(*reinterpret_cast<__half2*>(&a));
    float2 fb = __half22float2(*reinterpret_cast<__half2*>(&b));
    return fa.x * fb.x + fa.y * fb.y;
}

__device__ __forceinline__ uint32_t smem_u32(const void* p) {
    uint32_t a;
    asm("{ .reg .u64 t; cvta.to.shared.u64 t, %1; cvt.u32.u64 %0, t; }"
        : "=r"(a) : "l"(p));
    return a;
}

__device__ __forceinline__ float ex2f(float x) {
    float y;
    asm("ex2.approx.ftz.f32 %0, %1;" : "=f"(y) : "f"(x));
    return y;
}

__device__ __forceinline__ float lg2f(float x) {
    float y;
    asm("lg2.approx.ftz.f32 %0, %1;" : "=f"(y) : "f"(x));
    return y;
}

// ---------------------------------------------------------------------------
// main: persistent blocks; B staged once per block; per tile each warp owns
// its 16 rows end-to-end. A-fragment loads issued FIRST so their DRAM latency
// hides under the pos-dot gathers. f32 accum, scale applied in epilogue.
// ---------------------------------------------------------------------------
__global__ __launch_bounds__(256, 3) void main_kernel(
    const void* __restrict__ pos_idx,
    const void* __restrict__ neg_idx,
    float* __restrict__ out,
    int n, int ntiles)
{
    extern __shared__ char smem_raw[];
    __half* sV  = reinterpret_cast<__half*>(smem_raw);          // 256*136 fp16
    float* sPos = reinterpret_cast<float*>(sV + SNEG * STRIDE); // 128 floats
    float* sRed = sPos + MTILE;                                  // 8 floats
    int*   sLastP = reinterpret_cast<int*>(sRed + 8);

    const int tid  = threadIdx.x;
    const int lane = tid & 31;
    const int warp = tid >> 5;

    // ---- inline index-dtype detection (first 1KB of negatives) -------------
    int ok = 1;
    if (tid < 128) {
        long long v = ((const long long*)neg_idx)[tid];
        ok = (v >= 0 && v < (long long)n);
    }
    const int is64 = __syncthreads_and(ok);

    const int half16 = lane & 15;
    const int rsel   = lane >> 4;

    // ---- stage 256 negatives ONCE, coalesced, unscaled ----------------------
    {
#pragma unroll
        for (int i = 0; i < 16; i++) {
            int r = warp * 32 + 2 * i + rsel;
            long long vr = is64 ? ((const long long*)neg_idx)[r]
                                : (long long)((const int*)neg_idx)[r];
            uint4 v = *reinterpret_cast<const uint4*>(
                g_Qn + (size_t)vr * DIM + half16 * 8);
            *reinterpret_cast<uint4*>(sV + r * STRIDE + half16 * 8) = v;
        }
    }
    __syncthreads();

    // ldmatrix lane->row map (x4: two n-tiles x k lo/hi)
    const int nrow = (lane & 7) + ((lane & 16) >> 1);
    const uint32_t bAddr = smem_u32(sV) + nrow * (STRIDE * 2)
                         + ((lane & 8) << 1);

    const int g  = lane >> 2;
    const int t4 = lane & 3;

    float local = 0.0f;

    for (int tile = blockIdx.x; tile < ntiles; tile += GRIDP) {
        const long long tile0 = (long long)tile * MTILE;

        // ---- A fragments FIRST: loads in flight during the pos phase -------
        const long long rowG = tile0 + warp * 16 + g;
        unsigned afr[8][4];
        {
            long long r0 = rowG, r1 = rowG + 8;
            const bool v0 = r0 < n, v1 = r1 < n;
            const unsigned* p0 = reinterpret_cast<const unsigned*>(
                g_Qn + (size_t)r0 * DIM + 2 * t4);
            const unsigned* p1 = reinterpret_cast<const unsigned*>(
                g_Qn + (size_t)r1 * DIM + 2 * t4);
#pragma unroll
            for (int k0 = 0; k0 < 8; k0++) {
                afr[k0][0] = v0 ? p0[k0 * 8]     : 0u;
                afr[k0][1] = v1 ? p1[k0 * 8]     : 0u;
                afr[k0][2] = v0 ? p0[k0 * 8 + 4] : 0u;
                afr[k0][3] = v1 ? p1[k0 * 8 + 4] : 0u;
            }
        }

        // ---- positive logits for this warp's 16 rows (coalesced) -----------
#pragma unroll
        for (int i = 0; i < 8; i++) {
            int rloc = warp * 16 + 2 * i + rsel;
            long long row = tile0 + rloc;
            float d = 0.0f;
            if (row < n) {
                long long p = is64 ? ((const long long*)pos_idx)[row]
                                   : (long long)((const int*)pos_idx)[row];
                uint4 a = *reinterpret_cast<const uint4*>(
                    g_Qn + (size_t)row * DIM + half16 * 8);
                uint4 b = *reinterpret_cast<const uint4*>(
                    g_Qn + (size_t)p * DIM + half16 * 8);
                d = pairdot(a.x, b.x) + pairdot(a.y, b.y)
                  + pairdot(a.z, b.z) + pairdot(a.w, b.w);
            }
#pragma unroll
            for (int o = 8; o > 0; o >>= 1)
                d += __shfl_xor_sync(0xffffffffu, d, o);
            if (half16 == 0) sPos[rloc] = d * INV_T;
        }
        __syncwarp();   // sPos produced and consumed within this warp only

        // ---- GEMM: 8 chunks of 32 negatives, f32 accum ----------------------
        float rs0 = 0.0f, rs1 = 0.0f;
#pragma unroll
        for (int c = 0; c < 8; c++) {
            float acc[4][4];
#pragma unroll
            for (int i = 0; i < 4; i++) {
                acc[i][0] = 0.f; acc[i][1] = 0.f;
                acc[i][2] = 0.f; acc[i][3] = 0.f;
            }
#pragma unroll
            for (int k0 = 0; k0 < 8; k0++) {
#pragma unroll
                for (int nt2 = 0; nt2 < 2; nt2++) {
                    unsigned b0, b1, b2, b3;
                    uint32_t a = bAddr + (c * 32 + nt2 * 16) * (STRIDE * 2)
                               + k0 * 32;
                    asm volatile(
                        "ldmatrix.sync.aligned.m8n8.x4.shared.b16 "
                        "{%0,%1,%2,%3}, [%4];"
                        : "=r"(b0), "=r"(b1), "=r"(b2), "=r"(b3) : "r"(a));
                    asm volatile(
                        "mma.sync.aligned.m16n8k16.row.col.f32.f16.f16.f32 "
                        "{%0,%1,%2,%3}, {%4,%5,%6,%7}, {%8,%9}, {%0,%1,%2,%3};\n"
                        : "+f"(acc[nt2 * 2][0]), "+f"(acc[nt2 * 2][1]),
                          "+f"(acc[nt2 * 2][2]), "+f"(acc[nt2 * 2][3])
                        : "r"(afr[k0][0]), "r"(afr[k0][1]),
                          "r"(afr[k0][2]), "r"(afr[k0][3]),
                          "r"(b0), "r"(b1));
                    asm volatile(
                        "mma.sync.aligned.m16n8k16.row.col.f32.f16.f16.f32 "
                        "{%0,%1,%2,%3}, {%4,%5,%6,%7}, {%8,%9}, {%0,%1,%2,%3};\n"
                        : "+f"(acc[nt2 * 2 + 1][0]), "+f"(acc[nt2 * 2 + 1][1]),
                          "+f"(acc[nt2 * 2 + 1][2]), "+f"(acc[nt2 * 2 + 1][3])
                        : "r"(afr[k0][0]), "r"(afr[k0][1]),
                          "r"(afr[k0][2]), "r"(afr[k0][3]),
                          "r"(b2), "r"(b3));
                }
            }
            // epilogue: logits = dot*10; exp via ex2(dot * 10*log2e)
#pragma unroll
            for (int nt = 0; nt < 4; nt++) {
                rs0 += ex2f(acc[nt][0] * EXSCALE) + ex2f(acc[nt][1] * EXSCALE);
                rs1 += ex2f(acc[nt][2] * EXSCALE) + ex2f(acc[nt][3] * EXSCALE);
            }
        }

        rs0 += __shfl_xor_sync(0xffffffffu, rs0, 1);
        rs0 += __shfl_xor_sync(0xffffffffu, rs0, 2);
        rs1 += __shfl_xor_sync(0xffffffffu, rs1, 1);
        rs1 += __shfl_xor_sync(0xffffffffu, rs1, 2);

        if (t4 == 0) {
            if (rowG < n)
                local += sPos[warp * 16 + g]     - (lg2f(rs0) * LN2 - LOG_S);
            if (rowG + 8 < n)
                local += sPos[warp * 16 + g + 8] - (lg2f(rs1) * LN2 - LOG_S);
        }
    }

    // ---- deterministic block + grid reduction -------------------------------
#pragma unroll
    for (int o = 16; o > 0; o >>= 1)
        local += __shfl_xor_sync(0xffffffffu, local, o);
    if (lane == 0) sRed[warp] = local;
    __syncthreads();

    if (tid == 0) {
        float s = 0.0f;
#pragma unroll
        for (int w = 0; w < 8; w++) s += sRed[w];
        g_partial[blockIdx.x] = s;
        __threadfence();
        unsigned t = atomicAdd(&g_done, 1u);
        *sLastP = (t == (unsigned)(GRIDP - 1));
    }
    __syncthreads();
    if (*sLastP) {
        float s = 0.0f;
        for (int i = tid; i < GRIDP; i += 256) s += g_partial[i];
#pragma unroll
        for (int o = 16; o > 0; o >>= 1)
            s += __shfl_xor_sync(0xffffffffu, s, o);
        if (lane == 0) sRed[warp] = s;
        __syncthreads();
        if (tid == 0) {
            float tot = 0.f;
#pragma unroll
            for (int w = 0; w < 8; w++) tot += sRed[w];
            out[0] = -tot / (float)n;
            g_done = 0;                  // reset for next graph replay
        }
    }
}

// ---------------------------------------------------------------------------
extern "C" void kernel_launch(void* const* d_in, const int* in_sizes, int n_in,
                              void* d_out, int out_size) {
    const float* E   = (const float*)d_in[0];
    const void*  pos = d_in[1];
    const void*  neg = d_in[2];
    int n = in_sizes[1];   // number of edges

    int nblk_norm = (n + 15) / 16;   // 8 warps/block, 2 rows/warp
    normalize_kernel<<<nblk_norm, 256>>>(E, n);

    int ntiles = (n + MTILE - 1) / MTILE;
    size_t smem = (size_t)(SNEG * STRIDE) * sizeof(__half)
                + (size_t)(MTILE + 8 + 4) * sizeof(float);
    cudaFuncSetAttribute(main_kernel,
                         cudaFuncAttributeMaxDynamicSharedMemorySize, (int)smem);
    main_kernel<<<GRIDP, 256, smem>>>(pos, neg, (float*)d_out, n, ntiles);
}